// round 1
// baseline (speedup 1.0000x reference)
#include <cuda_runtime.h>
#include <cstdint>

#define BB 4
#define TT 2048
#define CC 1024
#define NH 16
#define HD 64
#define SCALE 0.125f

// Scratch (device globals: allocation-free rule)
__device__ float g_q[BB*NH*TT*HD];
__device__ float g_k[BB*NH*TT*HD];
__device__ float g_v[BB*NH*TT*HD];
__device__ float g_o[BB*NH*TT*HD];

// ---------------------------------------------------------------------------
// GEMM 1: qkv = x @ w_qkv   (M=8192, K=1024, N=3072)
// Epilogue scatters into g_q / g_k / g_v with [B,H,T,64] layout.
// 128x128 tile, BK=8, 256 threads, 8x8 per thread.
// ---------------------------------------------------------------------------
__global__ void __launch_bounds__(256) gemm_qkv_kernel(const float* __restrict__ A,
                                                       const float* __restrict__ W) {
    __shared__ float As[8][128];
    __shared__ float Bs[8][128];

    const int bn = blockIdx.x;   // 0..23
    const int bm = blockIdx.y;   // 0..63
    const int tid = threadIdx.x;
    const int tx = tid & 15;     // 0..15
    const int ty = tid >> 4;     // 0..15

    const int arow = tid >> 1;          // 0..127
    const int acol = (tid & 1) * 4;     // 0 or 4
    const int brow = tid >> 5;          // 0..7
    const int bcol = (tid & 31) * 4;    // 0..124

    const float* Ag = A + (size_t)(bm * 128 + arow) * 1024 + acol;
    const float* Bg = W + (size_t)brow * 3072 + bn * 128 + bcol;

    float acc[8][8];
    #pragma unroll
    for (int i = 0; i < 8; i++)
        #pragma unroll
        for (int j = 0; j < 8; j++) acc[i][j] = 0.f;

    for (int k0 = 0; k0 < 1024; k0 += 8) {
        float4 av = *(const float4*)(Ag + k0);
        float4 bv = *(const float4*)(Bg + (size_t)k0 * 3072);
        As[acol + 0][arow] = av.x;
        As[acol + 1][arow] = av.y;
        As[acol + 2][arow] = av.z;
        As[acol + 3][arow] = av.w;
        *(float4*)&Bs[brow][bcol] = bv;
        __syncthreads();

        #pragma unroll
        for (int kk = 0; kk < 8; kk++) {
            float4 a0 = *(const float4*)&As[kk][ty * 8];
            float4 a1 = *(const float4*)&As[kk][ty * 8 + 4];
            float4 b0 = *(const float4*)&Bs[kk][tx * 8];
            float4 b1 = *(const float4*)&Bs[kk][tx * 8 + 4];
            float af[8] = {a0.x, a0.y, a0.z, a0.w, a1.x, a1.y, a1.z, a1.w};
            float bf[8] = {b0.x, b0.y, b0.z, b0.w, b1.x, b1.y, b1.z, b1.w};
            #pragma unroll
            for (int i = 0; i < 8; i++)
                #pragma unroll
                for (int j = 0; j < 8; j++)
                    acc[i][j] += af[i] * bf[j];
        }
        __syncthreads();
    }

    // Epilogue: scatter to q/k/v  [B,H,T,64]
    #pragma unroll
    for (int i = 0; i < 8; i++) {
        const int mg = bm * 128 + ty * 8 + i;      // b*T + t
        const int b = mg >> 11;
        const int t = mg & 2047;
        #pragma unroll
        for (int j = 0; j < 8; j++) {
            const int ng = bn * 128 + tx * 8 + j;  // 0..3071
            const int which = ng >> 10;
            const int ccx = ng & 1023;
            const int h = ccx >> 6;
            const int dd = ccx & 63;
            float* dst = (which == 0) ? g_q : (which == 1) ? g_k : g_v;
            dst[((size_t)((b << 4) + h) * 2048 + t) * 64 + dd] = acc[i][j];
        }
    }
}

// ---------------------------------------------------------------------------
// Flash attention (fp32): one block per (bh, 64-query tile).
// 256 threads = 64 rows x 4 lanes; each lane owns 16 of the 64 d-components.
// Causal: only process k-tiles kt <= qt; mask diagonal tile.
// ---------------------------------------------------------------------------
__global__ void __launch_bounds__(256) attn_kernel(const unsigned char* __restrict__ mask) {
    const int qt = blockIdx.x;     // 0..31
    const int bh = blockIdx.y;     // 0..63
    const int b = bh >> 4;
    const int tid = threadIdx.x;
    const int row = tid >> 2;      // 0..63
    const int sub = tid & 3;       // 0..3
    const int qglob = qt * 64 + row;

    __shared__ float Ks[64 * 68];
    __shared__ float Vs[64 * 68];
    __shared__ float pad_s[64];

    // load + pre-scale my q slice
    const float* Qp = g_q + ((size_t)bh * 2048 + qglob) * 64 + sub * 16;
    float q[16];
    #pragma unroll
    for (int j = 0; j < 16; j++) q[j] = Qp[j] * SCALE;

    float o[16];
    #pragma unroll
    for (int j = 0; j < 16; j++) o[j] = 0.f;
    float m = -1e30f, l = 0.f;

    const float* Kbase = g_k + (size_t)bh * 2048 * 64;
    const float* Vbase = g_v + (size_t)bh * 2048 * 64;

    for (int kt = 0; kt <= qt; kt++) {
        __syncthreads();  // protect previous tile's shared data
        {
            // cooperative coalesced load: 1024 float4 per tile, 256 threads x 4
            const float4* Kg = (const float4*)(Kbase + (size_t)kt * 64 * 64);
            const float4* Vg = (const float4*)(Vbase + (size_t)kt * 64 * 64);
            #pragma unroll
            for (int i = 0; i < 4; i++) {
                int f = tid + 256 * i;        // 0..1023 flat float4 index
                int r = f >> 4;               // row 0..63
                int c4 = f & 15;              // float4 col 0..15
                ((float4*)Ks)[r * 17 + c4] = Kg[f];
                ((float4*)Vs)[r * 17 + c4] = Vg[f];
            }
            if (tid < 64)
                pad_s[tid] = mask[b * 2048 + kt * 64 + tid] ? -1e9f : 0.f;
        }
        __syncthreads();

        float s[64];
        #pragma unroll
        for (int kk = 0; kk < 64; kk++) {
            const float* Kr = Ks + kk * 68 + sub * 16;
            float acc = 0.f;
            #pragma unroll
            for (int j = 0; j < 16; j++) acc += q[j] * Kr[j];
            acc += __shfl_xor_sync(0xffffffffu, acc, 1);
            acc += __shfl_xor_sync(0xffffffffu, acc, 2);
            s[kk] = acc + pad_s[kk];
        }

        if (kt == qt) {
            #pragma unroll
            for (int kk = 0; kk < 64; kk++)
                if (kt * 64 + kk > qglob) s[kk] = -__int_as_float(0x7f800000); // -inf
        }

        float mtile = -1e30f;
        #pragma unroll
        for (int kk = 0; kk < 64; kk++) mtile = fmaxf(mtile, s[kk]);
        float mnew = fmaxf(m, mtile);
        float corr = __expf(m - mnew);
        l *= corr;
        #pragma unroll
        for (int j = 0; j < 16; j++) o[j] *= corr;
        m = mnew;

        #pragma unroll
        for (int kk = 0; kk < 64; kk++) {
            float p = __expf(s[kk] - mnew);
            l += p;
            s[kk] = p;
        }

        #pragma unroll
        for (int kk = 0; kk < 64; kk++) {
            const float p = s[kk];
            const float* Vr = Vs + kk * 68 + sub * 16;
            #pragma unroll
            for (int j = 0; j < 16; j++) o[j] += p * Vr[j];
        }
    }

    const float inv = 1.f / l;
    float* Op = g_o + ((size_t)bh * 2048 + qglob) * 64 + sub * 16;
    #pragma unroll
    for (int j = 0; j < 16; j++) Op[j] = o[j] * inv;
}

// ---------------------------------------------------------------------------
// GEMM 2: out = attn_out @ w_proj + b_proj  (M=8192, K=1024, N=1024)
// A gathered from g_o [B,H,T,64] (contiguous within a head -> float4 ok).
// ---------------------------------------------------------------------------
__global__ void __launch_bounds__(256) gemm_proj_kernel(const float* __restrict__ W,
                                                        const float* __restrict__ bias,
                                                        float* __restrict__ out) {
    __shared__ float As[8][128];
    __shared__ float Bs[8][128];

    const int bn = blockIdx.x;   // 0..7
    const int bm = blockIdx.y;   // 0..63
    const int tid = threadIdx.x;
    const int tx = tid & 15;
    const int ty = tid >> 4;

    const int arow = tid >> 1;
    const int acol = (tid & 1) * 4;
    const int brow = tid >> 5;
    const int bcol = (tid & 31) * 4;

    const int mg_l = bm * 128 + arow;     // b*T + t for my A-load row
    const int b_l = mg_l >> 11;
    const int t_l = mg_l & 2047;

    const float* Bg = W + (size_t)brow * 1024 + bn * 128 + bcol;

    float acc[8][8];
    #pragma unroll
    for (int i = 0; i < 8; i++)
        #pragma unroll
        for (int j = 0; j < 8; j++) acc[i][j] = 0.f;

    for (int k0 = 0; k0 < 1024; k0 += 8) {
        const int k = k0 + acol;          // 4-aligned, stays within one head
        const int h = k >> 6;
        const int dd = k & 63;
        float4 av = *(const float4*)(g_o + ((size_t)((b_l << 4) + h) * 2048 + t_l) * 64 + dd);
        float4 bv = *(const float4*)(Bg + (size_t)k0 * 1024);
        As[acol + 0][arow] = av.x;
        As[acol + 1][arow] = av.y;
        As[acol + 2][arow] = av.z;
        As[acol + 3][arow] = av.w;
        *(float4*)&Bs[brow][bcol] = bv;
        __syncthreads();

        #pragma unroll
        for (int kk = 0; kk < 8; kk++) {
            float4 a0 = *(const float4*)&As[kk][ty * 8];
            float4 a1 = *(const float4*)&As[kk][ty * 8 + 4];
            float4 b0 = *(const float4*)&Bs[kk][tx * 8];
            float4 b1 = *(const float4*)&Bs[kk][tx * 8 + 4];
            float af[8] = {a0.x, a0.y, a0.z, a0.w, a1.x, a1.y, a1.z, a1.w};
            float bf[8] = {b0.x, b0.y, b0.z, b0.w, b1.x, b1.y, b1.z, b1.w};
            #pragma unroll
            for (int i = 0; i < 8; i++)
                #pragma unroll
                for (int j = 0; j < 8; j++)
                    acc[i][j] += af[i] * bf[j];
        }
        __syncthreads();
    }

    #pragma unroll
    for (int i = 0; i < 8; i++) {
        const int mg = bm * 128 + ty * 8 + i;
        #pragma unroll
        for (int j = 0; j < 8; j++) {
            const int ng = bn * 128 + tx * 8 + j;
            out[(size_t)mg * 1024 + ng] = acc[i][j] + bias[ng];
        }
    }
}

// ---------------------------------------------------------------------------
extern "C" void kernel_launch(void* const* d_in, const int* in_sizes, int n_in,
                              void* d_out, int out_size) {
    (void)in_sizes; (void)n_in; (void)out_size;
    const float* x = (const float*)d_in[0];
    const unsigned char* mask = (const unsigned char*)d_in[1];
    const float* w_qkv = (const float*)d_in[2];
    const float* w_proj = (const float*)d_in[3];
    const float* b_proj = (const float*)d_in[4];
    float* out = (float*)d_out;

    gemm_qkv_kernel<<<dim3(24, 64), 256>>>(x, w_qkv);
    attn_kernel<<<dim3(32, 64), 256>>>(mask);
    gemm_proj_kernel<<<dim3(8, 64), 256>>>(w_proj, b_proj, out);
}

// round 2
// speedup vs baseline: 6.8482x; 6.8482x over previous
#include <cuda_runtime.h>
#include <cstdint>

#define SCALE 0.125f

// Scratch (device globals: allocation-free rule). Layout [B,H,T,64].
__device__ float g_q[4*16*2048*64];
__device__ float g_k[4*16*2048*64];
__device__ float g_v[4*16*2048*64];
__device__ float g_o[4*16*2048*64];

__device__ __forceinline__ unsigned f2tf(float f) {
    unsigned r; asm("cvt.rna.tf32.f32 %0, %1;" : "=r"(r) : "f"(f)); return r;
}

__device__ __forceinline__ void mma8(float* c, unsigned a0, unsigned a1, unsigned a2, unsigned a3,
                                     unsigned b0, unsigned b1) {
    asm volatile(
        "mma.sync.aligned.m16n8k8.row.col.f32.tf32.tf32.f32 "
        "{%0,%1,%2,%3},{%4,%5,%6,%7},{%8,%9},{%0,%1,%2,%3};\n"
        : "+f"(c[0]), "+f"(c[1]), "+f"(c[2]), "+f"(c[3])
        : "r"(a0), "r"(a1), "r"(a2), "r"(a3), "r"(b0), "r"(b1));
}

// ---------------------------------------------------------------------------
// tf32 GEMM: C[8192 x NTOT] = A[8192 x 1024] @ W[1024 x NTOT]
// ISQKV=true : A = x, epilogue scatters to g_q/g_k/g_v [B,H,T,64]
// ISQKV=false: A gathered from g_o [B,H,T,64], epilogue adds bias -> out
// Block tile 128x128, BK=16, 256 threads (warp grid 4M x 2N, warp tile 32x64).
// ---------------------------------------------------------------------------
template<int NTOT, bool ISQKV>
__global__ void __launch_bounds__(256) gemm_tf32(const float* __restrict__ A,
                                                 const float* __restrict__ W,
                                                 const float* __restrict__ bias,
                                                 float* __restrict__ out) {
    __shared__ unsigned As[16][136];   // [k][m], tf32 bits
    __shared__ unsigned Bs[16][136];   // [k][n], tf32 bits

    const int bn = blockIdx.x, bm = blockIdx.y;
    const int tid = threadIdx.x;
    const int w = tid >> 5, lane = tid & 31;
    const int gid = lane >> 2, tig = lane & 3;
    const int wm = w & 3, wn = w >> 2;

    float acc[2][8][4];
    #pragma unroll
    for (int mf = 0; mf < 2; mf++)
        #pragma unroll
        for (int nf = 0; nf < 8; nf++)
            #pragma unroll
            for (int j = 0; j < 4; j++) acc[mf][nf][j] = 0.f;

    // A-load mapping: f in [0,512): m = f>>2, kc = f&3 (k = kc*4)
    // B-load mapping: f in [0,512): kr = f>>5, n4 = f&31
    float4 aT[2], bT[2];

    auto loadA = [&](int k0, int i) -> float4 {
        const int f = tid + 256 * i;
        const int m = f >> 2, kc = f & 3;
        if constexpr (ISQKV) {
            return *(const float4*)(A + (size_t)(bm * 128 + m) * 1024 + k0 + kc * 4);
        } else {
            const int mg = bm * 128 + m;
            const int b = mg >> 11, t = mg & 2047;
            const int k = k0 + kc * 4;
            const int h = k >> 6, dd = k & 63;
            return *(const float4*)(g_o + ((size_t)((b << 4) + h) * 2048 + t) * 64 + dd);
        }
    };
    auto loadB = [&](int k0, int i) -> float4 {
        const int f = tid + 256 * i;
        const int kr = f >> 5, n4 = f & 31;
        return *(const float4*)(W + (size_t)(k0 + kr) * NTOT + bn * 128 + n4 * 4);
    };

    aT[0] = loadA(0, 0); aT[1] = loadA(0, 1);
    bT[0] = loadB(0, 0); bT[1] = loadB(0, 1);

    for (int k0 = 0; k0 < 1024; k0 += 16) {
        // store staged tile to smem (converting to tf32)
        #pragma unroll
        for (int i = 0; i < 2; i++) {
            const int f = tid + 256 * i;
            const int m = f >> 2, kc = f & 3;
            As[kc * 4 + 0][m] = f2tf(aT[i].x);
            As[kc * 4 + 1][m] = f2tf(aT[i].y);
            As[kc * 4 + 2][m] = f2tf(aT[i].z);
            As[kc * 4 + 3][m] = f2tf(aT[i].w);
            const int kr = f >> 5, n4 = f & 31;
            Bs[kr][n4 * 4 + 0] = f2tf(bT[i].x);
            Bs[kr][n4 * 4 + 1] = f2tf(bT[i].y);
            Bs[kr][n4 * 4 + 2] = f2tf(bT[i].z);
            Bs[kr][n4 * 4 + 3] = f2tf(bT[i].w);
        }
        __syncthreads();

        if (k0 + 16 < 1024) {
            aT[0] = loadA(k0 + 16, 0); aT[1] = loadA(k0 + 16, 1);
            bT[0] = loadB(k0 + 16, 0); bT[1] = loadB(k0 + 16, 1);
        }

        #pragma unroll
        for (int ks = 0; ks < 16; ks += 8) {
            unsigned af[2][4], bf[8][2];
            #pragma unroll
            for (int mf = 0; mf < 2; mf++) {
                const int row = wm * 32 + mf * 16 + gid;
                af[mf][0] = As[ks + tig][row];
                af[mf][1] = As[ks + tig][row + 8];
                af[mf][2] = As[ks + tig + 4][row];
                af[mf][3] = As[ks + tig + 4][row + 8];
            }
            #pragma unroll
            for (int nf = 0; nf < 8; nf++) {
                const int col = wn * 64 + nf * 8 + gid;
                bf[nf][0] = Bs[ks + tig][col];
                bf[nf][1] = Bs[ks + tig + 4][col];
            }
            #pragma unroll
            for (int mf = 0; mf < 2; mf++)
                #pragma unroll
                for (int nf = 0; nf < 8; nf++)
                    mma8(acc[mf][nf], af[mf][0], af[mf][1], af[mf][2], af[mf][3],
                         bf[nf][0], bf[nf][1]);
        }
        __syncthreads();
    }

    // Epilogue
    #pragma unroll
    for (int mf = 0; mf < 2; mf++) {
        const int r0 = bm * 128 + wm * 32 + mf * 16 + gid;
        const int r1 = r0 + 8;
        #pragma unroll
        for (int nf = 0; nf < 8; nf++) {
            const int cb = bn * 128 + wn * 64 + nf * 8 + 2 * tig;
            if constexpr (ISQKV) {
                #pragma unroll
                for (int rr = 0; rr < 2; rr++) {
                    const int r = rr ? r1 : r0;
                    const int b = r >> 11, t = r & 2047;
                    const int which = cb >> 10;
                    const int cx = cb & 1023;
                    const int h = cx >> 6, dd = cx & 63;
                    float* dst = (which == 0) ? g_q : (which == 1) ? g_k : g_v;
                    float2 v; v.x = acc[mf][nf][rr * 2]; v.y = acc[mf][nf][rr * 2 + 1];
                    *(float2*)(dst + ((size_t)((b << 4) + h) * 2048 + t) * 64 + dd) = v;
                }
            } else {
                const float2 bb = *(const float2*)(bias + cb);
                float2 v0; v0.x = acc[mf][nf][0] + bb.x; v0.y = acc[mf][nf][1] + bb.y;
                float2 v1; v1.x = acc[mf][nf][2] + bb.x; v1.y = acc[mf][nf][3] + bb.y;
                *(float2*)(out + (size_t)r0 * 1024 + cb) = v0;
                *(float2*)(out + (size_t)r1 * 1024 + cb) = v1;
            }
        }
    }
}

// ---------------------------------------------------------------------------
// Flash attention, tf32 tensor cores. Block = (q-tile of 64) x (bh), 4 warps.
// Each warp owns 16 q rows. S = Q K^T and O += P V via m16n8k8 mma.
// P round-trips through smem (reuses K buffer). Online softmax on C-frags.
// ---------------------------------------------------------------------------
__global__ void __launch_bounds__(128) attn_tc(const unsigned char* __restrict__ mask) {
    __shared__ unsigned Ks[64 * 68];   // K tile (tf32); reused for Q staging and P
    __shared__ unsigned Vs[64 * 72];   // V tile (tf32), stride 72 for bank-free B-frags
    __shared__ float pad_s[64];

    const int qt = blockIdx.x, bh = blockIdx.y, b = bh >> 4;
    const int tid = threadIdx.x, w = tid >> 5, lane = tid & 31;
    const int gid = lane >> 2, tig = lane & 3;
    const int r0l = w * 16 + gid;              // local row (0..63) for c0/c1
    const float NEG_INF = __int_as_float(0xff800000);

    const float* Qg = g_q + (size_t)bh * 2048 * 64;
    const float* Kg = g_k + (size_t)bh * 2048 * 64;
    const float* Vg = g_v + (size_t)bh * 2048 * 64;

    // ---- stage Q (scaled, tf32) via Ks, then load Q fragments ----
    {
        const float4* Q4 = (const float4*)(Qg + (size_t)qt * 64 * 64);
        #pragma unroll
        for (int i = 0; i < 8; i++) {
            const int f = tid + 128 * i;
            const int r = f >> 4, c4 = f & 15;
            float4 v = Q4[f];
            Ks[r * 68 + c4 * 4 + 0] = f2tf(v.x * SCALE);
            Ks[r * 68 + c4 * 4 + 1] = f2tf(v.y * SCALE);
            Ks[r * 68 + c4 * 4 + 2] = f2tf(v.z * SCALE);
            Ks[r * 68 + c4 * 4 + 3] = f2tf(v.w * SCALE);
        }
    }
    __syncthreads();
    unsigned qf[8][4];
    #pragma unroll
    for (int kf = 0; kf < 8; kf++) {
        qf[kf][0] = Ks[r0l * 68 + kf * 8 + tig];
        qf[kf][1] = Ks[(r0l + 8) * 68 + kf * 8 + tig];
        qf[kf][2] = Ks[r0l * 68 + kf * 8 + tig + 4];
        qf[kf][3] = Ks[(r0l + 8) * 68 + kf * 8 + tig + 4];
    }

    float o[8][4];
    #pragma unroll
    for (int nf = 0; nf < 8; nf++)
        #pragma unroll
        for (int j = 0; j < 4; j++) o[nf][j] = 0.f;
    float m0 = -1e30f, m1 = -1e30f, l0 = 0.f, l1 = 0.f;

    for (int kt = 0; kt <= qt; kt++) {
        __syncthreads();   // q-frag loads done (kt=0) / prev PV reads done

        // ---- load K, V tiles (tf32) + pad mask ----
        {
            const float4* K4 = (const float4*)(Kg + (size_t)kt * 64 * 64);
            const float4* V4 = (const float4*)(Vg + (size_t)kt * 64 * 64);
            #pragma unroll
            for (int i = 0; i < 8; i++) {
                const int f = tid + 128 * i;
                const int r = f >> 4, c4 = f & 15;
                float4 kv = K4[f];
                Ks[r * 68 + c4 * 4 + 0] = f2tf(kv.x);
                Ks[r * 68 + c4 * 4 + 1] = f2tf(kv.y);
                Ks[r * 68 + c4 * 4 + 2] = f2tf(kv.z);
                Ks[r * 68 + c4 * 4 + 3] = f2tf(kv.w);
                float4 vv = V4[f];
                Vs[r * 72 + c4 * 4 + 0] = f2tf(vv.x);
                Vs[r * 72 + c4 * 4 + 1] = f2tf(vv.y);
                Vs[r * 72 + c4 * 4 + 2] = f2tf(vv.z);
                Vs[r * 72 + c4 * 4 + 3] = f2tf(vv.w);
            }
            if (tid < 64)
                pad_s[tid] = mask[b * 2048 + kt * 64 + tid] ? -1e9f : 0.f;
        }
        __syncthreads();

        // ---- S = Q K^T ----
        float s[8][4];
        #pragma unroll
        for (int nf = 0; nf < 8; nf++) {
            s[nf][0] = 0.f; s[nf][1] = 0.f; s[nf][2] = 0.f; s[nf][3] = 0.f;
            #pragma unroll
            for (int kf = 0; kf < 8; kf++) {
                const unsigned kb0 = Ks[(nf * 8 + gid) * 68 + kf * 8 + tig];
                const unsigned kb1 = Ks[(nf * 8 + gid) * 68 + kf * 8 + tig + 4];
                mma8(s[nf], qf[kf][0], qf[kf][1], qf[kf][2], qf[kf][3], kb0, kb1);
            }
        }

        // ---- pad + causal mask ----
        #pragma unroll
        for (int nf = 0; nf < 8; nf++) {
            const float p0 = pad_s[nf * 8 + 2 * tig];
            const float p1 = pad_s[nf * 8 + 2 * tig + 1];
            s[nf][0] += p0; s[nf][1] += p1; s[nf][2] += p0; s[nf][3] += p1;
        }
        if (kt == qt) {
            const int rg0 = qt * 64 + r0l, rg1 = rg0 + 8;
            #pragma unroll
            for (int nf = 0; nf < 8; nf++) {
                const int cg = kt * 64 + nf * 8 + 2 * tig;
                if (cg > rg0)     s[nf][0] = NEG_INF;
                if (cg + 1 > rg0) s[nf][1] = NEG_INF;
                if (cg > rg1)     s[nf][2] = NEG_INF;
                if (cg + 1 > rg1) s[nf][3] = NEG_INF;
            }
        }

        // ---- online softmax ----
        float mt0 = -1e30f, mt1 = -1e30f;
        #pragma unroll
        for (int nf = 0; nf < 8; nf++) {
            mt0 = fmaxf(mt0, fmaxf(s[nf][0], s[nf][1]));
            mt1 = fmaxf(mt1, fmaxf(s[nf][2], s[nf][3]));
        }
        mt0 = fmaxf(mt0, __shfl_xor_sync(0xffffffffu, mt0, 1));
        mt0 = fmaxf(mt0, __shfl_xor_sync(0xffffffffu, mt0, 2));
        mt1 = fmaxf(mt1, __shfl_xor_sync(0xffffffffu, mt1, 1));
        mt1 = fmaxf(mt1, __shfl_xor_sync(0xffffffffu, mt1, 2));
        const float mn0 = fmaxf(m0, mt0), mn1 = fmaxf(m1, mt1);
        const float cor0 = __expf(m0 - mn0), cor1 = __expf(m1 - mn1);
        float rs0 = 0.f, rs1 = 0.f;
        #pragma unroll
        for (int nf = 0; nf < 8; nf++) {
            s[nf][0] = __expf(s[nf][0] - mn0); rs0 += s[nf][0];
            s[nf][1] = __expf(s[nf][1] - mn0); rs0 += s[nf][1];
            s[nf][2] = __expf(s[nf][2] - mn1); rs1 += s[nf][2];
            s[nf][3] = __expf(s[nf][3] - mn1); rs1 += s[nf][3];
        }
        rs0 += __shfl_xor_sync(0xffffffffu, rs0, 1);
        rs0 += __shfl_xor_sync(0xffffffffu, rs0, 2);
        rs1 += __shfl_xor_sync(0xffffffffu, rs1, 1);
        rs1 += __shfl_xor_sync(0xffffffffu, rs1, 2);
        l0 = l0 * cor0 + rs0; l1 = l1 * cor1 + rs1;
        m0 = mn0; m1 = mn1;
        #pragma unroll
        for (int nf = 0; nf < 8; nf++) {
            o[nf][0] *= cor0; o[nf][1] *= cor0; o[nf][2] *= cor1; o[nf][3] *= cor1;
        }

        __syncthreads();   // everyone done reading Ks (S-mma)

        // ---- store P (tf32) into Ks ----
        #pragma unroll
        for (int nf = 0; nf < 8; nf++) {
            const int cb = nf * 8 + 2 * tig;
            Ks[r0l * 68 + cb]           = f2tf(s[nf][0]);
            Ks[r0l * 68 + cb + 1]       = f2tf(s[nf][1]);
            Ks[(r0l + 8) * 68 + cb]     = f2tf(s[nf][2]);
            Ks[(r0l + 8) * 68 + cb + 1] = f2tf(s[nf][3]);
        }
        __syncthreads();

        // ---- O += P V ----
        #pragma unroll
        for (int kf = 0; kf < 8; kf++) {
            const unsigned pa0 = Ks[r0l * 68 + kf * 8 + tig];
            const unsigned pa1 = Ks[(r0l + 8) * 68 + kf * 8 + tig];
            const unsigned pa2 = Ks[r0l * 68 + kf * 8 + tig + 4];
            const unsigned pa3 = Ks[(r0l + 8) * 68 + kf * 8 + tig + 4];
            #pragma unroll
            for (int nf = 0; nf < 8; nf++) {
                const unsigned vb0 = Vs[(kf * 8 + tig) * 72 + nf * 8 + gid];
                const unsigned vb1 = Vs[(kf * 8 + tig + 4) * 72 + nf * 8 + gid];
                mma8(o[nf], pa0, pa1, pa2, pa3, vb0, vb1);
            }
        }
    }

    // ---- normalize + write O ----
    const float inv0 = 1.f / l0, inv1 = 1.f / l1;
    float* Op = g_o + ((size_t)bh * 2048 + qt * 64) * 64;
    #pragma unroll
    for (int nf = 0; nf < 8; nf++) {
        const int cb = nf * 8 + 2 * tig;
        float2 v0; v0.x = o[nf][0] * inv0; v0.y = o[nf][1] * inv0;
        float2 v1; v1.x = o[nf][2] * inv1; v1.y = o[nf][3] * inv1;
        *(float2*)(Op + (size_t)r0l * 64 + cb) = v0;
        *(float2*)(Op + (size_t)(r0l + 8) * 64 + cb) = v1;
    }
}

// ---------------------------------------------------------------------------
extern "C" void kernel_launch(void* const* d_in, const int* in_sizes, int n_in,
                              void* d_out, int out_size) {
    (void)in_sizes; (void)n_in; (void)out_size;
    const float* x = (const float*)d_in[0];
    const unsigned char* mask = (const unsigned char*)d_in[1];
    const float* w_qkv = (const float*)d_in[2];
    const float* w_proj = (const float*)d_in[3];
    const float* b_proj = (const float*)d_in[4];
    float* out = (float*)d_out;

    gemm_tf32<3072, true><<<dim3(24, 64), 256>>>(x, w_qkv, nullptr, nullptr);
    attn_tc<<<dim3(32, 64), 128>>>(mask);
    gemm_tf32<1024, false><<<dim3(8, 64), 256>>>(nullptr, w_proj, b_proj, out);
}